// round 8
// baseline (speedup 1.0000x reference)
#include <cuda_runtime.h>

// Problem constants
#define BB    8
#define TT    2048
#define CIN   7
#define CC    8
#define NCH   128      // chunks per batch
#define SEGC  4        // chunks per segment
#define SEGSTEPS 64    // time steps per segment
#define NSEGS 32       // segments per batch
#define NBLK  256      // persistent blocks
#define NT    512      // threads per block
#define SIZE  4680     // 8 + 64 + 512 + 4096
#define STRIDE 4736    // padded row stride (floats)
#define O2    8
#define O3    72
#define O4    584
#define HDIM  256
#define NSL   32       // gemv slices
#define SLW   147      // slice width (32*147 = 4704 >= 4680)

// Scratch (device globals -- no runtime allocation)
__device__ __align__(16) float g_bufB[(size_t)BB * NCH * STRIDE];   // local prefixes
__device__ __align__(16) float g_bufA[(size_t)BB * NCH * STRIDE];   // logs
__device__ __align__(16) float g_T[(size_t)BB * NSEGS * STRIDE];    // scanned totals
__device__ __align__(16) float g_hp[NSL * BB * HDIM];
__device__ unsigned int g_bar;   // zero-init; reset at end of every launch

// ---------------------------------------------------------------------------
// Device-wide barrier (all NBLK blocks call; co-residency guaranteed by
// __launch_bounds__(NT,2): 148 SMs * 2 = 296 >= 256).
// ---------------------------------------------------------------------------
__device__ __forceinline__ void gsync(unsigned int idx)
{
    __syncthreads();
    if (threadIdx.x == 0) {
        __threadfence();
        atomicAdd(&g_bar, 1u);
        unsigned int target = idx * NBLK;
        volatile unsigned int* p = &g_bar;
        while (*p < target) { }
        __threadfence();
    }
    __syncthreads();
}

// ---------------------------------------------------------------------------
// Group merge Od = A (x) B (full levels). 512 threads.
// smem: al at sm, bl at sm+584. Cross-block reads via __ldcg.
// ---------------------------------------------------------------------------
__device__ void ta_merge(const float* __restrict__ A, const float* __restrict__ Bp,
                         float* __restrict__ Od, float* sm, int tid)
{
    float* al = sm;
    float* bl = sm + 584;
    for (int t = tid; t < O4; t += NT) { al[t] = __ldcg(A + t); bl[t] = __ldcg(Bp + t); }
    __syncthreads();

    for (int t = tid; t < O4; t += NT) {
        float r;
        if (t >= O3) {
            int q = t - O3;
            r = al[t] + bl[t] + al[q >> 6] * bl[O2 + (q & 63)]
              + al[O2 + (q >> 3)] * bl[q & 7];
        } else if (t >= O2) {
            int u = t - O2;
            r = al[t] + bl[t] + al[u >> 3] * bl[u & 7];
        } else {
            r = al[t] + bl[t];
        }
        Od[t] = r;
    }
    float a1r[8];
    #pragma unroll
    for (int i = 0; i < 8; i++) a1r[i] = al[i];
    float4 b1v = *(const float4*)&bl[(4 * tid) & 7];
    float4 b2v = *(const float4*)&bl[O2 + ((4 * tid) & 63)];
    float4 b3v = *(const float4*)&bl[O3 + 4 * (tid & 127)];
    #pragma unroll
    for (int m2 = 0; m2 < 2; m2++) {
        int p = 4 * tid + 2048 * m2;
        float a1 = a1r[(tid >> 7) + 4 * m2];
        float a2 = al[O2 + (tid >> 4) + 32 * m2];
        float a3 = al[O3 + (tid >> 1) + 256 * m2];
        float4 Av = __ldcg((const float4*)(A + O4 + p));
        float4 Bv = __ldcg((const float4*)(Bp + O4 + p));
        float4 o;
        o.x = Av.x + Bv.x + a1 * b3v.x + a2 * b2v.x + a3 * b1v.x;
        o.y = Av.y + Bv.y + a1 * b3v.y + a2 * b2v.y + a3 * b1v.y;
        o.z = Av.z + Bv.z + a1 * b3v.z + a2 * b2v.z + a3 * b1v.z;
        o.w = Av.w + Bv.w + a1 * b3v.w + a2 * b2v.w + a3 * b1v.w;
        *(float4*)(Od + O4 + p) = o;
    }
}

// ---------------------------------------------------------------------------
// apply+log for one chunk task. 512 threads. sm: 2848 floats.
// ---------------------------------------------------------------------------
__device__ void apply_one(int task, float* sm, int tid)
{
    int b = task >> 7, n = task & 127;
    int seg = n >> 2;                 // SEGC = 4

    float* s    = sm;                 // 584
    float* al   = sm + 584;           // 584
    float* blw  = sm + 1168;          // 584
    float* P2_2 = sm + 1752;          // 64 (+pad)
    float* P2_3 = sm + 1824;          // 512
    float* P3_3 = sm + 2336;          // 512

    const float* L = g_bufB + (size_t)task * STRIDE;
    float4 r4v[2];

    if (seg == 0) {
        for (int t = tid; t < O4; t += NT) s[t] = __ldcg(L + t);
        #pragma unroll
        for (int m2 = 0; m2 < 2; m2++)
            r4v[m2] = __ldcg((const float4*)(L + O4 + 4 * tid + 2048 * m2));
    } else {
        const float* A = (seg == 1)
            ? g_bufB + (size_t)(b * NCH + SEGC - 1) * STRIDE
            : g_T + (size_t)(b * NSEGS + seg - 1) * STRIDE;
        for (int t = tid; t < O4; t += NT) { al[t] = __ldcg(A + t); blw[t] = __ldcg(L + t); }
        __syncthreads();
        for (int t = tid; t < O4; t += NT) {
            float r;
            if (t >= O3) {
                int q = t - O3;
                r = al[t] + blw[t]
                  + al[q >> 6]        * blw[O2 + (q & 63)]
                  + al[O2 + (q >> 3)] * blw[q & 7];
            } else if (t >= O2) {
                int u = t - O2;
                r = al[t] + blw[t] + al[u >> 3] * blw[u & 7];
            } else {
                r = al[t] + blw[t];
            }
            s[t] = r;
        }
        float a1r[8];
        #pragma unroll
        for (int i = 0; i < 8; i++) a1r[i] = al[i];
        float4 b1v = *(const float4*)&blw[(4 * tid) & 7];
        float4 b2v = *(const float4*)&blw[O2 + ((4 * tid) & 63)];
        float4 b3v = *(const float4*)&blw[O3 + 4 * (tid & 127)];
        #pragma unroll
        for (int m2 = 0; m2 < 2; m2++) {
            int p = 4 * tid + 2048 * m2;
            float a1 = a1r[(tid >> 7) + 4 * m2];
            float a2 = al[O2 + (tid >> 4) + 32 * m2];
            float a3 = al[O3 + (tid >> 1) + 256 * m2];
            float4 Av = __ldcg((const float4*)(A + O4 + p));
            float4 Lv = __ldcg((const float4*)(L + O4 + p));
            float4 o;
            o.x = Av.x + Lv.x + a1 * b3v.x + a2 * b2v.x + a3 * b1v.x;
            o.y = Av.y + Lv.y + a1 * b3v.y + a2 * b2v.y + a3 * b1v.y;
            o.z = Av.z + Lv.z + a1 * b3v.z + a2 * b2v.z + a3 * b1v.z;
            o.w = Av.w + Lv.w + a1 * b3v.w + a2 * b2v.w + a3 * b1v.w;
            r4v[m2] = o;
        }
    }
    __syncthreads();

    // ---- truncated log, folded into r4v ----
    float s1r[8];
    #pragma unroll
    for (int i = 0; i < 8; i++) s1r[i] = s[i];
    float4 s1v = *(const float4*)&s[(4 * tid) & 7];
    float4 s2v = *(const float4*)&s[O2 + ((4 * tid) & 63)];
    float4 s3v = *(const float4*)&s[O3 + 4 * (tid & 127)];
    float s2f = s[O2 + (tid & 63)], s1f = s[tid & 7];
    float s3s = s[O3 + tid];

    // p2: fold -1/2 p2_L4; store p2 lows
    #pragma unroll
    for (int m2 = 0; m2 < 2; m2++) {
        float a1 = s1r[(tid >> 7) + 4 * m2];
        float a2 = s[O2 + (tid >> 4) + 32 * m2];
        float a3 = s[O3 + (tid >> 1) + 256 * m2];
        r4v[m2].x -= 0.5f * (a1 * s3v.x + a2 * s2v.x + a3 * s1v.x);
        r4v[m2].y -= 0.5f * (a1 * s3v.y + a2 * s2v.y + a3 * s1v.y);
        r4v[m2].z -= 0.5f * (a1 * s3v.z + a2 * s2v.z + a3 * s1v.z);
        r4v[m2].w -= 0.5f * (a1 * s3v.w + a2 * s2v.w + a3 * s1v.w);
    }
    P2_3[tid] = s1r[tid >> 6] * s2f + s[O2 + (tid >> 3)] * s1f;
    if (tid < 64) P2_2[tid] = s1r[tid >> 3] * s[tid & 7];
    __syncthreads();

    // p3: fold +1/3 p3_L4; store p3 level 3
    {
        float4 P23v = *(const float4*)&P2_3[4 * (tid & 127)];
        float4 P22v = *(const float4*)&P2_2[(4 * tid) & 63];
        #pragma unroll
        for (int m2 = 0; m2 < 2; m2++) {
            float a1 = s1r[(tid >> 7) + 4 * m2];
            float a2 = s[O2 + (tid >> 4) + 32 * m2];
            r4v[m2].x += (1.0f / 3.0f) * (a1 * P23v.x + a2 * P22v.x);
            r4v[m2].y += (1.0f / 3.0f) * (a1 * P23v.y + a2 * P22v.y);
            r4v[m2].z += (1.0f / 3.0f) * (a1 * P23v.z + a2 * P22v.z);
            r4v[m2].w += (1.0f / 3.0f) * (a1 * P23v.w + a2 * P22v.w);
        }
        P3_3[tid] = s1r[tid >> 6] * P2_2[tid & 63];
    }
    __syncthreads();

    // p4: fold -1/4 p4_L4; write out
    float* S = g_bufA + (size_t)task * STRIDE;
    {
        float4 P33v = *(const float4*)&P3_3[4 * (tid & 127)];
        #pragma unroll
        for (int m2 = 0; m2 < 2; m2++) {
            float a1 = s1r[(tid >> 7) + 4 * m2];
            r4v[m2].x -= 0.25f * a1 * P33v.x;
            r4v[m2].y -= 0.25f * a1 * P33v.y;
            r4v[m2].z -= 0.25f * a1 * P33v.z;
            r4v[m2].w -= 0.25f * a1 * P33v.w;
            *(float4*)&S[O4 + 4 * tid + 2048 * m2] = r4v[m2];
        }
        S[O3 + tid] = s3s - 0.5f * P2_3[tid] + (1.0f / 3.0f) * P3_3[tid];
    }
    if (tid < 64) S[O2 + tid] = s[O2 + tid] - 0.5f * P2_2[tid];
    if (tid < 8)  S[tid] = s1r[tid];
}

// ---------------------------------------------------------------------------
// THE single fused kernel. 256 blocks x 512 threads, 2 blocks/SM forced.
// ---------------------------------------------------------------------------
__global__ void __launch_bounds__(NT, 2)
k_fused(const float* __restrict__ x,
        const float* __restrict__ W1,
        const float* __restrict__ b1,
        const float* __restrict__ W2,
        const float* __restrict__ b2,
        float* __restrict__ out)
{
    __shared__ __align__(16) float sm[2848];
    int blk = blockIdx.x;
    int tid = threadIdx.x;

    // warm L2 with W1 for phase 4
    {
        size_t nbytes = (size_t)SIZE * HDIM * 4;
        size_t loff = ((size_t)blk * NT + tid) * 64;
        if (loff < nbytes)
            asm volatile("prefetch.global.L2 [%0];" :: "l"((const char*)W1 + loff));
    }

    // ======================= Phase 1: Chen over segment =====================
    // 256 blocks = (b, seg); 64 steps; snapshots every 16 steps are the local
    // chunk prefixes. 512 threads: L4 p = tid + 512*m, m=0..7:
    //   l = p&7 = tid&7, k = (p>>3)&7 = (tid>>3)&7, j = (p>>6)&7 = tid>>6 (const!),
    //   i = p>>9 = m; p>>3 = (tid>>3)+64m; p>>6 = (tid>>6)+8m.
    {
        int b = blk >> 5, seg = blk & 31;
        float* d = sm;          // [64][8] = 512
        float* c = sm + 512;    // O4 lows

        for (int idx = tid; idx < SEGSTEPS * CC; idx += NT) {
            int s = idx >> 3, ch = idx & 7;
            int t = seg * SEGSTEPS + s;
            float v;
            if (ch < CIN) {
                float cur  = x[(b * TT + t) * CIN + ch];
                float prev = (t > 0) ? x[(b * TT + t - 1) * CIN + ch] : 0.0f;
                v = cur - prev;
            } else {
                v = (t > 0) ? (1.0f / 2047.0f) : 0.0f;
            }
            d[idx] = v;
        }
        __syncthreads();

        const int l = tid & 7, k = (tid >> 3) & 7, j = tid >> 6;
        float r4[8];
        {
            float d8[8];
            #pragma unroll
            for (int i = 0; i < 8; i++) d8[i] = d[i];
            float dl = d8[l], dkl = d8[k] * dl, dj = d8[j], djkl = dj * dkl;
            #pragma unroll
            for (int m = 0; m < 8; m++) r4[m] = d8[m] * djkl * (1.0f / 24.0f);
            c[O3 + tid] = djkl * (1.0f / 6.0f);
            if (tid < 64) c[O2 + tid] = d8[tid >> 3] * d8[tid & 7] * 0.5f;
            if (tid < 8)  c[tid] = d8[tid];
        }

        for (int s = 1; s < SEGSTEPS; s++) {
            __syncthreads();
            float d8[8], c1r[8];
            #pragma unroll
            for (int i = 0; i < 8; i++) d8[i] = d[s * 8 + i];
            #pragma unroll
            for (int i = 0; i < 8; i++) c1r[i] = c[i];
            float dl = d8[l], dkl = d8[k] * dl, dj = d8[j];
            float djkl = dj * dkl;
            float hdkl = 0.5f * dkl;
            float sdjkl = djkl * (1.0f / 6.0f);
            float qdjkl = djkl * (1.0f / 24.0f);
            #pragma unroll
            for (int m = 0; m < 8; m++) {
                float c3 = c[O3 + (tid >> 3) + 64 * m];
                float c2 = c[O2 + (tid >> 6) + 8 * m];
                r4[m] += c3 * dl + c2 * hdkl + c1r[m] * sdjkl + d8[m] * qdjkl;
            }
            float t3 = c[O3 + tid] + c[O2 + (tid >> 3)] * dl + c1r[j] * hdkl + sdjkl;
            float t2 = 0.0f, t1 = 0.0f;
            if (tid < 64) t2 = c[O2 + tid] + c1r[tid >> 3] * d8[tid & 7]
                             + d8[tid >> 3] * d8[tid & 7] * 0.5f;
            if (tid < 8)  t1 = c1r[tid] + d8[tid];
            __syncthreads();
            c[O3 + tid] = t3;
            if (tid < 64) c[O2 + tid] = t2;
            if (tid < 8)  c[tid] = t1;

            if ((s & 15) == 15) {   // snapshot = local prefix of chunk (s>>4)
                float* o = g_bufB + (size_t)((b * NSEGS + seg) * SEGC + (s >> 4)) * STRIDE;
                o[O3 + tid] = t3;
                if (tid < 64) o[O2 + tid] = t2;
                if (tid < 8)  o[tid] = t1;
                #pragma unroll
                for (int m = 0; m < 8; m++) o[O4 + tid + 512 * m] = r4[m];
            }
        }
    }
    gsync(1);

    // ======================= Phase 2: Sklansky over 32 ======================
    for (int r = 0; r < 5; r++) {
        if (blk < 128) {
            int b = blk >> 4, g = blk & 15;
            int span = 1 << r;
            int e_src = ((g >> r) << (r + 1)) + span - 1;
            int e_dst = ((g >> r) << (r + 1)) + span + (g & (span - 1));
            bool bnew = (g & (span - 1)) == 0;
            const float* A = (r == 0)
                ? g_bufB + (size_t)((b * NSEGS + e_src) * SEGC + SEGC - 1) * STRIDE
                : g_T + (size_t)(b * NSEGS + e_src) * STRIDE;
            const float* Bp = bnew
                ? g_bufB + (size_t)((b * NSEGS + e_dst) * SEGC + SEGC - 1) * STRIDE
                : g_T + (size_t)(b * NSEGS + e_dst) * STRIDE;
            float* Od = g_T + (size_t)(b * NSEGS + e_dst) * STRIDE;
            ta_merge(A, Bp, Od, sm, tid);
        }
        gsync(2 + r);
    }

    // ======================= Phase 3: apply + log ===========================
    for (int it = 0; it < 4; it++) {
        __syncthreads();
        apply_one(blk + 256 * it, sm, tid);
    }
    gsync(7);

    // ======================= Phase 4: pool + GEMV partials ==================
    {
        int b = blk >> 5, sl = blk & 31;
        int i0 = sl * SLW;
        int len = SIZE - i0; if (len > SLW) len = SLW;
        float* pv  = sm;         // 160
        float* sm2 = sm + 160;   // 512
        __syncthreads();
        for (int t = tid; t < len; t += NT) {
            const float* p = g_bufA + (size_t)b * NCH * STRIDE + i0 + t;
            float acc = 0.0f;
            #pragma unroll 8
            for (int n = 0; n < NCH; n++) acc += __ldcg(p + (size_t)n * STRIDE);
            pv[t] = acc * (1.0f / NCH);
        }
        __syncthreads();
        int g2 = tid >> 8, j = tid & 255;
        float acc = 0.0f;
        for (int ii = g2; ii < len; ii += 2)
            acc = fmaf(pv[ii], __ldg(&W1[(size_t)(i0 + ii) * HDIM + j]), acc);
        sm2[g2 * 256 + j] = acc;
        __syncthreads();
        if (tid < 256)
            g_hp[(sl * BB + b) * HDIM + tid] = sm2[tid] + sm2[256 + tid];
    }
    gsync(8);

    // ======================= Final: MLP head (block 0) ======================
    if (blk == 0) {
        float* red = sm;
        __syncthreads();
        for (int bb = 0; bb < BB; bb++) {
            if (tid < 256) {
                float h = 0.0f;
                #pragma unroll
                for (int sl2 = 0; sl2 < NSL; sl2++)
                    h += __ldcg(&g_hp[(sl2 * BB + bb) * HDIM + tid]);
                red[tid] = fmaxf(h + b1[tid], 0.0f) * W2[tid];
            }
            __syncthreads();
            for (int s2 = 128; s2 > 0; s2 >>= 1) {
                if (tid < s2) red[tid] += red[tid + s2];
                __syncthreads();
            }
            if (tid == 0) out[bb] = red[0] + b2[0];
            __syncthreads();
        }
        if (tid == 0) g_bar = 0u;   // reset for next graph replay
    }
}

// ---------------------------------------------------------------------------
extern "C" void kernel_launch(void* const* d_in, const int* in_sizes, int n_in,
                              void* d_out, int out_size)
{
    const float* x  = (const float*)d_in[0];
    const float* W1 = (const float*)d_in[1];
    const float* b1 = (const float*)d_in[2];
    const float* W2 = (const float*)d_in[3];
    const float* b2 = (const float*)d_in[4];
    float* out = (float*)d_out;

    (void)in_sizes; (void)n_in; (void)out_size;

    k_fused<<<NBLK, NT>>>(x, W1, b1, W2, b2, out);
}

// round 9
// speedup vs baseline: 1.4967x; 1.4967x over previous
#include <cuda_runtime.h>

// Problem constants
#define BB    8
#define TT    2048
#define CIN   7
#define CC    8
#define NCH   128      // chunks per batch
#define SEGC  2        // chunks per segment
#define SEGST 32       // time steps per segment
#define NSEG2 64       // segments per batch
#define NBLK  256      // persistent blocks
#define NT    256      // threads per block
#define SIZE  4680
#define STRIDE 4736
#define O2    8
#define O3    72
#define O4    584
#define HDIM  256
#define NSL   32       // gemv slices
#define SLW   147

#define NTASK1 (BB * NSEG2)    // 512 chen tasks
#define NTASK3 (BB * NCH)      // 1024 apply tasks
#define NTASK4 (BB * NSL)      // 256 pool/gemv tasks

// Scratch (device globals -- no runtime allocation)
__device__ __align__(16) float g_bufB[(size_t)BB * NCH * STRIDE];   // local prefixes
__device__ __align__(16) float g_bufA[(size_t)BB * NCH * STRIDE];   // logs
__device__ __align__(16) float g_T[(size_t)BB * NSEG2 * STRIDE];    // scanned totals
__device__ __align__(16) float g_hp[NSL * BB * HDIM];
__device__ unsigned int g_bar;    // all zero-init; reset at end of launch
__device__ unsigned int g_t1, g_t3, g_t4;

// ---------------------------------------------------------------------------
// Device-wide barrier (co-residency: __launch_bounds__(256,2) -> 296 >= 256)
// ---------------------------------------------------------------------------
__device__ __forceinline__ void gsync(unsigned int idx)
{
    __syncthreads();
    if (threadIdx.x == 0) {
        __threadfence();
        atomicAdd(&g_bar, 1u);
        unsigned int target = idx * NBLK;
        volatile unsigned int* p = &g_bar;
        while (*p < target) { }
        __threadfence();
    }
    __syncthreads();
}

// ---------------------------------------------------------------------------
// Group merge Od = A (x) B. 256 threads. smem: al, bl (584 each).
// ---------------------------------------------------------------------------
__device__ void ta_merge(const float* __restrict__ A, const float* __restrict__ Bp,
                         float* __restrict__ Od, float* sm, int tid)
{
    float* al = sm;
    float* bl = sm + 584;
    for (int t = tid; t < O4; t += NT) { al[t] = __ldcg(A + t); bl[t] = __ldcg(Bp + t); }
    __syncthreads();

    for (int t = tid; t < O4; t += NT) {
        float r;
        if (t >= O3) {
            int q = t - O3;
            r = al[t] + bl[t] + al[q >> 6] * bl[O2 + (q & 63)]
              + al[O2 + (q >> 3)] * bl[q & 7];
        } else if (t >= O2) {
            int u = t - O2;
            r = al[t] + bl[t] + al[u >> 3] * bl[u & 7];
        } else {
            r = al[t] + bl[t];
        }
        Od[t] = r;
    }
    float a1r[8];
    #pragma unroll
    for (int i = 0; i < 8; i++) a1r[i] = al[i];
    float4 b1v = *(const float4*)&bl[(4 * tid) & 7];
    float4 b2v = *(const float4*)&bl[O2 + ((4 * tid) & 63)];
    float4 b3v = *(const float4*)&bl[O3 + 4 * (tid & 127)];
    #pragma unroll
    for (int m4 = 0; m4 < 4; m4++) {
        int p = 4 * tid + 1024 * m4;
        float a1 = a1r[(tid >> 7) + 2 * m4];
        float a2 = al[O2 + (tid >> 4) + 16 * m4];
        float a3 = al[O3 + (tid >> 1) + 128 * m4];
        float4 Av = __ldcg((const float4*)(A + O4 + p));
        float4 Bv = __ldcg((const float4*)(Bp + O4 + p));
        float4 o;
        o.x = Av.x + Bv.x + a1 * b3v.x + a2 * b2v.x + a3 * b1v.x;
        o.y = Av.y + Bv.y + a1 * b3v.y + a2 * b2v.y + a3 * b1v.y;
        o.z = Av.z + Bv.z + a1 * b3v.z + a2 * b2v.z + a3 * b1v.z;
        o.w = Av.w + Bv.w + a1 * b3v.w + a2 * b2v.w + a3 * b1v.w;
        *(float4*)(Od + O4 + p) = o;
    }
}

// ---------------------------------------------------------------------------
// apply+log for one chunk task. 256 threads. sm: 2848 floats.
// ---------------------------------------------------------------------------
__device__ void apply_one(int task, float* sm, int tid)
{
    int b = task >> 7, n = task & 127;
    int seg = n >> 1;                 // SEGC = 2

    float* s    = sm;
    float* al   = sm + 584;
    float* blw  = sm + 1168;
    float* P2_2 = sm + 1752;
    float* P2_3 = sm + 1824;
    float* P3_3 = sm + 2336;

    const float* L = g_bufB + (size_t)task * STRIDE;
    float4 r4v[4];

    if (seg == 0) {
        for (int t = tid; t < O4; t += NT) s[t] = __ldcg(L + t);
        #pragma unroll
        for (int m4 = 0; m4 < 4; m4++)
            r4v[m4] = __ldcg((const float4*)(L + O4 + 4 * tid + 1024 * m4));
    } else {
        const float* A = (seg == 1)
            ? g_bufB + (size_t)(b * NCH + 1) * STRIDE
            : g_T + (size_t)(b * NSEG2 + seg - 1) * STRIDE;
        for (int t = tid; t < O4; t += NT) { al[t] = __ldcg(A + t); blw[t] = __ldcg(L + t); }
        __syncthreads();
        for (int t = tid; t < O4; t += NT) {
            float r;
            if (t >= O3) {
                int q = t - O3;
                r = al[t] + blw[t]
                  + al[q >> 6]        * blw[O2 + (q & 63)]
                  + al[O2 + (q >> 3)] * blw[q & 7];
            } else if (t >= O2) {
                int u = t - O2;
                r = al[t] + blw[t] + al[u >> 3] * blw[u & 7];
            } else {
                r = al[t] + blw[t];
            }
            s[t] = r;
        }
        float a1r[8];
        #pragma unroll
        for (int i = 0; i < 8; i++) a1r[i] = al[i];
        float4 b1v = *(const float4*)&blw[(4 * tid) & 7];
        float4 b2v = *(const float4*)&blw[O2 + ((4 * tid) & 63)];
        float4 b3v = *(const float4*)&blw[O3 + 4 * (tid & 127)];
        #pragma unroll
        for (int m4 = 0; m4 < 4; m4++) {
            int p = 4 * tid + 1024 * m4;
            float a1 = a1r[(tid >> 7) + 2 * m4];
            float a2 = al[O2 + (tid >> 4) + 16 * m4];
            float a3 = al[O3 + (tid >> 1) + 128 * m4];
            float4 Av = __ldcg((const float4*)(A + O4 + p));
            float4 Lv = __ldcg((const float4*)(L + O4 + p));
            float4 o;
            o.x = Av.x + Lv.x + a1 * b3v.x + a2 * b2v.x + a3 * b1v.x;
            o.y = Av.y + Lv.y + a1 * b3v.y + a2 * b2v.y + a3 * b1v.y;
            o.z = Av.z + Lv.z + a1 * b3v.z + a2 * b2v.z + a3 * b1v.z;
            o.w = Av.w + Lv.w + a1 * b3v.w + a2 * b2v.w + a3 * b1v.w;
            r4v[m4] = o;
        }
    }
    __syncthreads();

    float s1r[8];
    #pragma unroll
    for (int i = 0; i < 8; i++) s1r[i] = s[i];
    float4 s1v = *(const float4*)&s[(4 * tid) & 7];
    float4 s2v = *(const float4*)&s[O2 + ((4 * tid) & 63)];
    float4 s3v = *(const float4*)&s[O3 + 4 * (tid & 127)];
    float s2f = s[O2 + (tid & 63)], s1f = s[tid & 7];
    float s3a = s[O3 + tid], s3b = s[O3 + tid + 256];

    #pragma unroll
    for (int m4 = 0; m4 < 4; m4++) {
        float a1 = s1r[(tid >> 7) + 2 * m4];
        float a2 = s[O2 + (tid >> 4) + 16 * m4];
        float a3 = s[O3 + (tid >> 1) + 128 * m4];
        r4v[m4].x -= 0.5f * (a1 * s3v.x + a2 * s2v.x + a3 * s1v.x);
        r4v[m4].y -= 0.5f * (a1 * s3v.y + a2 * s2v.y + a3 * s1v.y);
        r4v[m4].z -= 0.5f * (a1 * s3v.z + a2 * s2v.z + a3 * s1v.z);
        r4v[m4].w -= 0.5f * (a1 * s3v.w + a2 * s2v.w + a3 * s1v.w);
    }
    {
        float pa = s1r[tid >> 6] * s2f + s[O2 + (tid >> 3)] * s1f;
        float pb = s1r[(tid >> 6) + 4] * s2f + s[O2 + (tid >> 3) + 32] * s1f;
        P2_3[tid] = pa; P2_3[tid + 256] = pb;
    }
    if (tid < 64) P2_2[tid] = s1r[tid >> 3] * s[tid & 7];
    __syncthreads();

    {
        float4 P23v = *(const float4*)&P2_3[4 * (tid & 127)];
        float4 P22v = *(const float4*)&P2_2[(4 * tid) & 63];
        #pragma unroll
        for (int m4 = 0; m4 < 4; m4++) {
            float a1 = s1r[(tid >> 7) + 2 * m4];
            float a2 = s[O2 + (tid >> 4) + 16 * m4];
            r4v[m4].x += (1.0f / 3.0f) * (a1 * P23v.x + a2 * P22v.x);
            r4v[m4].y += (1.0f / 3.0f) * (a1 * P23v.y + a2 * P22v.y);
            r4v[m4].z += (1.0f / 3.0f) * (a1 * P23v.z + a2 * P22v.z);
            r4v[m4].w += (1.0f / 3.0f) * (a1 * P23v.w + a2 * P22v.w);
        }
        float P22a = P2_2[tid & 63];
        P3_3[tid]       = s1r[tid >> 6] * P22a;
        P3_3[tid + 256] = s1r[(tid >> 6) + 4] * P22a;
    }
    __syncthreads();

    float* S = g_bufA + (size_t)task * STRIDE;
    {
        float4 P33v = *(const float4*)&P3_3[4 * (tid & 127)];
        #pragma unroll
        for (int m4 = 0; m4 < 4; m4++) {
            float a1 = s1r[(tid >> 7) + 2 * m4];
            r4v[m4].x -= 0.25f * a1 * P33v.x;
            r4v[m4].y -= 0.25f * a1 * P33v.y;
            r4v[m4].z -= 0.25f * a1 * P33v.z;
            r4v[m4].w -= 0.25f * a1 * P33v.w;
            *(float4*)&S[O4 + 4 * tid + 1024 * m4] = r4v[m4];
        }
        S[O3 + tid]       = s3a - 0.5f * P2_3[tid]       + (1.0f / 3.0f) * P3_3[tid];
        S[O3 + tid + 256] = s3b - 0.5f * P2_3[tid + 256] + (1.0f / 3.0f) * P3_3[tid + 256];
    }
    if (tid < 64) S[O2 + tid] = s[O2 + tid] - 0.5f * P2_2[tid];
    if (tid < 8)  S[tid] = s1r[tid];
}

// ---------------------------------------------------------------------------
// THE single fused kernel. 256 blocks x 256 threads, work-stealing phases.
// ---------------------------------------------------------------------------
__global__ void __launch_bounds__(NT, 2)
k_fused(const float* __restrict__ x,
        const float* __restrict__ W1,
        const float* __restrict__ b1,
        const float* __restrict__ W2,
        const float* __restrict__ b2,
        float* __restrict__ out)
{
    __shared__ __align__(16) float sm[2848];
    __shared__ int s_task;
    int blk = blockIdx.x;
    int tid = threadIdx.x;

    // warm L2 with W1 for phase 4
    {
        size_t nbytes = (size_t)SIZE * HDIM * 4;
        size_t loff = ((size_t)blk * NT + tid) * 128;
        if (loff < nbytes)
            asm volatile("prefetch.global.L2 [%0];" :: "l"((const char*)W1 + loff));
    }

    // ============ Phase 1: 2-step-fused Chen, 512 stolen tasks =============
    // Task = 32-step segment (b, seg). Two-step factor F = exp(a)(x)exp(b)
    // computed in registers; carry L4 in regs, lows ping-pong in smem.
    // L4 element p = tid + 256*m: l=tid&7, k=(tid>>3)&7, j=j0+4*(m&1), i=m>>1.
    {
        const int l = tid & 7, k = (tid >> 3) & 7, j0 = tid >> 6;
        float* d   = sm;          // 256 = [32][8]
        float* cb0 = sm + 256;    // c2 [0,64), c3 [64,576)
        float* cb1 = sm + 840;
        for (;;) {
            __syncthreads();
            if (tid == 0) s_task = (int)atomicAdd(&g_t1, 1u);
            __syncthreads();
            int task = s_task;
            if (task >= NTASK1) break;
            int b = task >> 6, seg = task & 63;

            {   // increments (one per thread: 32 steps x 8 ch = 256)
                int s = tid >> 3, ch = tid & 7;
                int t = seg * SEGST + s;
                float v;
                if (ch < CIN) {
                    float cur  = __ldg(&x[(b * TT + t) * CIN + ch]);
                    float prev = (t > 0) ? __ldg(&x[(b * TT + t - 1) * CIN + ch]) : 0.0f;
                    v = cur - prev;
                } else {
                    v = (t > 0) ? (1.0f / 2047.0f) : 0.0f;
                }
                d[tid] = v;
            }
            __syncthreads();

            float r4[16], c1r[8];
            // ---- iter 0: carry := F(d0, d1) ----
            {
                float a8[8], b8[8];
                #pragma unroll
                for (int i = 0; i < 8; i++) { a8[i] = d[i]; b8[i] = d[8 + i]; }
                float al = a8[l], bl = b8[l], ak = a8[k], bk = b8[k];
                float bkbl = bk * bl;
                float w1 = ak * ((1.0f / 6.0f) * al + 0.5f * bl) + 0.5f * bkbl;
                float w2 = (1.0f / 6.0f) * bkbl;
                float aje = a8[j0], bje = b8[j0], ajo = a8[j0 + 4], bjo = b8[j0 + 4];
                float F3_e = aje * w1 + bje * w2;
                float F3_o = ajo * w1 + bjo * w2;
                float u4 = ak * ((1.0f / 24.0f) * al + (1.0f / 6.0f) * bl) + 0.25f * bkbl;
                float v4 = (1.0f / 6.0f) * bkbl;
                float ge = aje * u4 + bje * v4, he = (1.0f / 24.0f) * bje * bkbl;
                float go = ajo * u4 + bjo * v4, ho = (1.0f / 24.0f) * bjo * bkbl;
                #pragma unroll
                for (int m = 0; m < 16; m++)
                    r4[m] = a8[m >> 1] * ((m & 1) ? go : ge) + b8[m >> 1] * ((m & 1) ? ho : he);
                #pragma unroll
                for (int i = 0; i < 8; i++) c1r[i] = a8[i] + b8[i];
                cb0[64 + tid] = F3_e;
                cb0[64 + tid + 256] = F3_o;
                if (tid < 64) {
                    int xx = tid >> 3, yy = tid & 7;
                    cb0[tid] = 0.5f * a8[xx] * a8[yy] + a8[xx] * b8[yy] + 0.5f * b8[xx] * b8[yy];
                }
                __syncthreads();
            }
            // ---- iters 1..15 ----
            for (int it = 1; it < 16; it++) {
                float* cc = (it & 1) ? cb0 : cb1;
                float* cn = (it & 1) ? cb1 : cb0;
                float a8[8], b8[8];
                #pragma unroll
                for (int i = 0; i < 8; i++) { a8[i] = d[16 * it + i]; b8[i] = d[16 * it + 8 + i]; }
                float al = a8[l], bl = b8[l], ak = a8[k], bk = b8[k];
                float el = al + bl;
                float bkbl = bk * bl;
                float F2_kl = 0.5f * ak * al + ak * bl + 0.5f * bkbl;
                float w1 = ak * ((1.0f / 6.0f) * al + 0.5f * bl) + 0.5f * bkbl;
                float w2 = (1.0f / 6.0f) * bkbl;
                float aje = a8[j0], bje = b8[j0], ajo = a8[j0 + 4], bjo = b8[j0 + 4];
                float F3_e = aje * w1 + bje * w2;
                float F3_o = ajo * w1 + bjo * w2;
                float u4 = ak * ((1.0f / 24.0f) * al + (1.0f / 6.0f) * bl) + 0.25f * bkbl;
                float v4 = (1.0f / 6.0f) * bkbl;
                float ge = aje * u4 + bje * v4, he = (1.0f / 24.0f) * bje * bkbl;
                float go = ajo * u4 + bjo * v4, ho = (1.0f / 24.0f) * bjo * bkbl;
                #pragma unroll
                for (int m = 0; m < 16; m++) {
                    float c3v = cc[64 + (tid >> 3) + 32 * m];
                    float c2v = cc[(tid >> 6) + 4 * m];
                    float F3j = (m & 1) ? F3_o : F3_e;
                    float F4m = a8[m >> 1] * ((m & 1) ? go : ge) + b8[m >> 1] * ((m & 1) ? ho : he);
                    r4[m] += F4m + c1r[m >> 1] * F3j + c2v * F2_kl + c3v * el;
                }
                float t3a = cc[64 + tid] + F3_e + cc[tid >> 3] * el + c1r[j0] * F2_kl;
                float t3b = cc[64 + tid + 256] + F3_o + cc[(tid >> 3) + 32] * el + c1r[j0 + 4] * F2_kl;
                float t2v = 0.0f;
                if (tid < 64) {
                    int xx = tid >> 3, yy = tid & 7;
                    t2v = cc[tid] + 0.5f * a8[xx] * a8[yy] + a8[xx] * b8[yy] + 0.5f * b8[xx] * b8[yy]
                        + c1r[xx] * (a8[yy] + b8[yy]);
                }
                #pragma unroll
                for (int i = 0; i < 8; i++) c1r[i] += a8[i] + b8[i];
                cn[64 + tid] = t3a;
                cn[64 + tid + 256] = t3b;
                if (tid < 64) cn[tid] = t2v;
                __syncthreads();
                if ((it & 7) == 7) {   // chunk snapshot (steps 0..15 / 0..31)
                    float* o = g_bufB + (size_t)(b * NCH + seg * SEGC + (it >> 3)) * STRIDE;
                    o[O3 + tid] = t3a;
                    o[O3 + tid + 256] = t3b;
                    if (tid < 64) o[O2 + tid] = t2v;
                    if (tid < 8)  o[tid] = c1r[tid];
                    #pragma unroll
                    for (int m = 0; m < 16; m++) o[O4 + tid + 256 * m] = r4[m];
                }
            }
        }
    }
    gsync(1);

    // ============ Phase 2: Sklansky over 64 segment totals ==================
    // 6 rounds; each round exactly 256 merges (32 per batch) = 1 per block.
    for (int r = 0; r < 6; r++) {
        int b = blk >> 5, g = blk & 31;
        int span = 1 << r;
        int base = (g >> r) << (r + 1);
        int e_src = base + span - 1;
        int e_dst = base + span + (g & (span - 1));
        bool bnew = (g & (span - 1)) == 0;
        const float* A = (r == 0)
            ? g_bufB + (size_t)(b * NCH + e_src * SEGC + SEGC - 1) * STRIDE
            : g_T + (size_t)(b * NSEG2 + e_src) * STRIDE;
        const float* Bp = bnew
            ? g_bufB + (size_t)(b * NCH + e_dst * SEGC + SEGC - 1) * STRIDE
            : g_T + (size_t)(b * NSEG2 + e_dst) * STRIDE;
        float* Od = g_T + (size_t)(b * NSEG2 + e_dst) * STRIDE;
        __syncthreads();
        ta_merge(A, Bp, Od, sm, tid);
        gsync(2 + r);
    }

    // ============ Phase 3: apply + log, 1024 stolen tasks ===================
    for (;;) {
        __syncthreads();
        if (tid == 0) s_task = (int)atomicAdd(&g_t3, 1u);
        __syncthreads();
        int task = s_task;
        if (task >= NTASK3) break;
        apply_one(task, sm, tid);
    }
    gsync(8);

    // ============ Phase 4: pool + GEMV partials, 256 stolen tasks ===========
    for (;;) {
        __syncthreads();
        if (tid == 0) s_task = (int)atomicAdd(&g_t4, 1u);
        __syncthreads();
        int task = s_task;
        if (task >= NTASK4) break;
        int b = task >> 5, sl = task & 31;
        int i0 = sl * SLW;
        int len = SIZE - i0; if (len > SLW) len = SLW;
        float* pv = sm;
        if (tid < len) {
            const float* p = g_bufA + (size_t)b * NCH * STRIDE + i0 + tid;
            float acc = 0.0f;
            #pragma unroll 8
            for (int n = 0; n < NCH; n++) acc += __ldcg(p + (size_t)n * STRIDE);
            pv[tid] = acc * (1.0f / NCH);
        }
        __syncthreads();
        float acc = 0.0f;
        for (int ii = 0; ii < len; ii++)
            acc = fmaf(pv[ii], __ldg(&W1[(size_t)(i0 + ii) * HDIM + tid]), acc);
        g_hp[(sl * BB + b) * HDIM + tid] = acc;
    }
    gsync(9);

    // ============ Final: MLP head (block 0) =================================
    if (blk == 0) {
        float* red = sm;
        __syncthreads();
        for (int bb = 0; bb < BB; bb++) {
            float h = 0.0f;
            #pragma unroll
            for (int sl2 = 0; sl2 < NSL; sl2++)
                h += __ldcg(&g_hp[(sl2 * BB + bb) * HDIM + tid]);
            float v = fmaxf(h + b1[tid], 0.0f) * W2[tid];
            red[tid] = v; __syncthreads();
            for (int s2 = 128; s2 > 0; s2 >>= 1) {
                if (tid < s2) red[tid] += red[tid + s2];
                __syncthreads();
            }
            if (tid == 0) out[bb] = red[0] + b2[0];
            __syncthreads();
        }
        if (tid == 0) { g_bar = 0u; g_t1 = 0u; g_t3 = 0u; g_t4 = 0u; }
    }
}

// ---------------------------------------------------------------------------
extern "C" void kernel_launch(void* const* d_in, const int* in_sizes, int n_in,
                              void* d_out, int out_size)
{
    const float* x  = (const float*)d_in[0];
    const float* W1 = (const float*)d_in[1];
    const float* b1 = (const float*)d_in[2];
    const float* W2 = (const float*)d_in[3];
    const float* b2 = (const float*)d_in[4];
    float* out = (float*)d_out;

    (void)in_sizes; (void)n_in; (void)out_size;

    k_fused<<<NBLK, NT>>>(x, W1, b1, W2, b2, out);
}

// round 10
// speedup vs baseline: 1.7040x; 1.1385x over previous
#include <cuda_runtime.h>

// Problem constants
#define BB    8
#define TT    2048
#define CIN   7
#define CC    8
#define NCH   128      // chunks per batch
#define SEGC  2        // chunks per segment
#define SEGST 32       // time steps per segment
#define NSEG2 64       // segments per batch
#define NBLK  384      // persistent blocks (3/SM on 128 SMs, 2/SM on rest)
#define NT    256      // threads per block
#define SIZE  4680
#define STRIDE 4736
#define O2    8
#define O3    72
#define O4    584
#define HDIM  256
#define NSL   32       // gemv slices
#define SLW   147

#define NTASK1 (BB * NSEG2)    // 512 chen tasks
#define NTASK3 (BB * NCH)      // 1024 apply tasks
#define NTASK4 (BB * NSL)      // 256 pool/gemv tasks

// Scratch (device globals -- no runtime allocation)
__device__ __align__(16) float g_bufB[(size_t)BB * NCH * STRIDE];   // local prefixes
__device__ __align__(16) float g_bufA[(size_t)BB * NCH * STRIDE];   // logs
__device__ __align__(16) float g_T[(size_t)BB * NSEG2 * STRIDE];    // scanned totals
__device__ __align__(16) float g_hp[NSL * BB * HDIM];
__device__ unsigned int g_bar;    // all zero-init; reset at end of launch
__device__ unsigned int g_t1, g_t3, g_t4;

// ---------------------------------------------------------------------------
// Device-wide barrier. Co-residency: __launch_bounds__(256,3) -> 444 >= 384.
// ---------------------------------------------------------------------------
__device__ __forceinline__ void gsync(unsigned int idx)
{
    __syncthreads();
    if (threadIdx.x == 0) {
        __threadfence();
        atomicAdd(&g_bar, 1u);
        unsigned int target = idx * NBLK;
        volatile unsigned int* p = &g_bar;
        while (*p < target) { }
        __threadfence();
    }
    __syncthreads();
}

// ---------------------------------------------------------------------------
// Group merge Od = A (x) B. 256 threads. smem: al, bl (584 each).
// ---------------------------------------------------------------------------
__device__ void ta_merge(const float* __restrict__ A, const float* __restrict__ Bp,
                         float* __restrict__ Od, float* sm, int tid)
{
    float* al = sm;
    float* bl = sm + 584;
    for (int t = tid; t < O4; t += NT) { al[t] = __ldcg(A + t); bl[t] = __ldcg(Bp + t); }
    __syncthreads();

    for (int t = tid; t < O4; t += NT) {
        float r;
        if (t >= O3) {
            int q = t - O3;
            r = al[t] + bl[t] + al[q >> 6] * bl[O2 + (q & 63)]
              + al[O2 + (q >> 3)] * bl[q & 7];
        } else if (t >= O2) {
            int u = t - O2;
            r = al[t] + bl[t] + al[u >> 3] * bl[u & 7];
        } else {
            r = al[t] + bl[t];
        }
        Od[t] = r;
    }
    float a1r[8];
    #pragma unroll
    for (int i = 0; i < 8; i++) a1r[i] = al[i];
    float4 b1v = *(const float4*)&bl[(4 * tid) & 7];
    float4 b2v = *(const float4*)&bl[O2 + ((4 * tid) & 63)];
    float4 b3v = *(const float4*)&bl[O3 + 4 * (tid & 127)];
    #pragma unroll
    for (int m4 = 0; m4 < 4; m4++) {
        int p = 4 * tid + 1024 * m4;
        float a1 = a1r[(tid >> 7) + 2 * m4];
        float a2 = al[O2 + (tid >> 4) + 16 * m4];
        float a3 = al[O3 + (tid >> 1) + 128 * m4];
        float4 Av = __ldcg((const float4*)(A + O4 + p));
        float4 Bv = __ldcg((const float4*)(Bp + O4 + p));
        float4 o;
        o.x = Av.x + Bv.x + a1 * b3v.x + a2 * b2v.x + a3 * b1v.x;
        o.y = Av.y + Bv.y + a1 * b3v.y + a2 * b2v.y + a3 * b1v.y;
        o.z = Av.z + Bv.z + a1 * b3v.z + a2 * b2v.z + a3 * b1v.z;
        o.w = Av.w + Bv.w + a1 * b3v.w + a2 * b2v.w + a3 * b1v.w;
        *(float4*)(Od + O4 + p) = o;
    }
}

// ---------------------------------------------------------------------------
// apply+log for one chunk task. 256 threads. sm: 2848 floats.
// ---------------------------------------------------------------------------
__device__ void apply_one(int task, float* sm, int tid)
{
    int b = task >> 7, n = task & 127;
    int seg = n >> 1;                 // SEGC = 2

    float* s    = sm;
    float* al   = sm + 584;
    float* blw  = sm + 1168;
    float* P2_2 = sm + 1752;
    float* P2_3 = sm + 1824;
    float* P3_3 = sm + 2336;

    const float* L = g_bufB + (size_t)task * STRIDE;
    float4 r4v[4];

    if (seg == 0) {
        for (int t = tid; t < O4; t += NT) s[t] = __ldcg(L + t);
        #pragma unroll
        for (int m4 = 0; m4 < 4; m4++)
            r4v[m4] = __ldcg((const float4*)(L + O4 + 4 * tid + 1024 * m4));
    } else {
        const float* A = (seg == 1)
            ? g_bufB + (size_t)(b * NCH + 1) * STRIDE
            : g_T + (size_t)(b * NSEG2 + seg - 1) * STRIDE;
        for (int t = tid; t < O4; t += NT) { al[t] = __ldcg(A + t); blw[t] = __ldcg(L + t); }
        __syncthreads();
        for (int t = tid; t < O4; t += NT) {
            float r;
            if (t >= O3) {
                int q = t - O3;
                r = al[t] + blw[t]
                  + al[q >> 6]        * blw[O2 + (q & 63)]
                  + al[O2 + (q >> 3)] * blw[q & 7];
            } else if (t >= O2) {
                int u = t - O2;
                r = al[t] + blw[t] + al[u >> 3] * blw[u & 7];
            } else {
                r = al[t] + blw[t];
            }
            s[t] = r;
        }
        float a1r[8];
        #pragma unroll
        for (int i = 0; i < 8; i++) a1r[i] = al[i];
        float4 b1v = *(const float4*)&blw[(4 * tid) & 7];
        float4 b2v = *(const float4*)&blw[O2 + ((4 * tid) & 63)];
        float4 b3v = *(const float4*)&blw[O3 + 4 * (tid & 127)];
        #pragma unroll
        for (int m4 = 0; m4 < 4; m4++) {
            int p = 4 * tid + 1024 * m4;
            float a1 = a1r[(tid >> 7) + 2 * m4];
            float a2 = al[O2 + (tid >> 4) + 16 * m4];
            float a3 = al[O3 + (tid >> 1) + 128 * m4];
            float4 Av = __ldcg((const float4*)(A + O4 + p));
            float4 Lv = __ldcg((const float4*)(L + O4 + p));
            float4 o;
            o.x = Av.x + Lv.x + a1 * b3v.x + a2 * b2v.x + a3 * b1v.x;
            o.y = Av.y + Lv.y + a1 * b3v.y + a2 * b2v.y + a3 * b1v.y;
            o.z = Av.z + Lv.z + a1 * b3v.z + a2 * b2v.z + a3 * b1v.z;
            o.w = Av.w + Lv.w + a1 * b3v.w + a2 * b2v.w + a3 * b1v.w;
            r4v[m4] = o;
        }
    }
    __syncthreads();

    float s1r[8];
    #pragma unroll
    for (int i = 0; i < 8; i++) s1r[i] = s[i];
    float4 s1v = *(const float4*)&s[(4 * tid) & 7];
    float4 s2v = *(const float4*)&s[O2 + ((4 * tid) & 63)];
    float4 s3v = *(const float4*)&s[O3 + 4 * (tid & 127)];
    float s2f = s[O2 + (tid & 63)], s1f = s[tid & 7];
    float s3a = s[O3 + tid], s3b = s[O3 + tid + 256];

    #pragma unroll
    for (int m4 = 0; m4 < 4; m4++) {
        float a1 = s1r[(tid >> 7) + 2 * m4];
        float a2 = s[O2 + (tid >> 4) + 16 * m4];
        float a3 = s[O3 + (tid >> 1) + 128 * m4];
        r4v[m4].x -= 0.5f * (a1 * s3v.x + a2 * s2v.x + a3 * s1v.x);
        r4v[m4].y -= 0.5f * (a1 * s3v.y + a2 * s2v.y + a3 * s1v.y);
        r4v[m4].z -= 0.5f * (a1 * s3v.z + a2 * s2v.z + a3 * s1v.z);
        r4v[m4].w -= 0.5f * (a1 * s3v.w + a2 * s2v.w + a3 * s1v.w);
    }
    {
        float pa = s1r[tid >> 6] * s2f + s[O2 + (tid >> 3)] * s1f;
        float pb = s1r[(tid >> 6) + 4] * s2f + s[O2 + (tid >> 3) + 32] * s1f;
        P2_3[tid] = pa; P2_3[tid + 256] = pb;
    }
    if (tid < 64) P2_2[tid] = s1r[tid >> 3] * s[tid & 7];
    __syncthreads();

    {
        float4 P23v = *(const float4*)&P2_3[4 * (tid & 127)];
        float4 P22v = *(const float4*)&P2_2[(4 * tid) & 63];
        #pragma unroll
        for (int m4 = 0; m4 < 4; m4++) {
            float a1 = s1r[(tid >> 7) + 2 * m4];
            float a2 = s[O2 + (tid >> 4) + 16 * m4];
            r4v[m4].x += (1.0f / 3.0f) * (a1 * P23v.x + a2 * P22v.x);
            r4v[m4].y += (1.0f / 3.0f) * (a1 * P23v.y + a2 * P22v.y);
            r4v[m4].z += (1.0f / 3.0f) * (a1 * P23v.z + a2 * P22v.z);
            r4v[m4].w += (1.0f / 3.0f) * (a1 * P23v.w + a2 * P22v.w);
        }
        float P22a = P2_2[tid & 63];
        P3_3[tid]       = s1r[tid >> 6] * P22a;
        P3_3[tid + 256] = s1r[(tid >> 6) + 4] * P22a;
    }
    __syncthreads();

    float* S = g_bufA + (size_t)task * STRIDE;
    {
        float4 P33v = *(const float4*)&P3_3[4 * (tid & 127)];
        #pragma unroll
        for (int m4 = 0; m4 < 4; m4++) {
            float a1 = s1r[(tid >> 7) + 2 * m4];
            r4v[m4].x -= 0.25f * a1 * P33v.x;
            r4v[m4].y -= 0.25f * a1 * P33v.y;
            r4v[m4].z -= 0.25f * a1 * P33v.z;
            r4v[m4].w -= 0.25f * a1 * P33v.w;
            *(float4*)&S[O4 + 4 * tid + 1024 * m4] = r4v[m4];
        }
        S[O3 + tid]       = s3a - 0.5f * P2_3[tid]       + (1.0f / 3.0f) * P3_3[tid];
        S[O3 + tid + 256] = s3b - 0.5f * P2_3[tid + 256] + (1.0f / 3.0f) * P3_3[tid + 256];
    }
    if (tid < 64) S[O2 + tid] = s[O2 + tid] - 0.5f * P2_2[tid];
    if (tid < 8)  S[tid] = s1r[tid];
}

// ---------------------------------------------------------------------------
// THE single fused kernel. 384 blocks x 256 threads (3/SM), work-stealing.
// ---------------------------------------------------------------------------
__global__ void __launch_bounds__(NT, 3)
k_fused(const float* __restrict__ x,
        const float* __restrict__ W1,
        const float* __restrict__ b1,
        const float* __restrict__ W2,
        const float* __restrict__ b2,
        float* __restrict__ out)
{
    __shared__ __align__(16) float sm[2848];
    __shared__ int s_task;
    int blk = blockIdx.x;
    int tid = threadIdx.x;

    // warm L2 with W1 for phase 4
    {
        size_t nbytes = (size_t)SIZE * HDIM * 4;
        size_t loff = ((size_t)blk * NT + tid) * 128;
        if (loff < nbytes)
            asm volatile("prefetch.global.L2 [%0];" :: "l"((const char*)W1 + loff));
    }

    // ============ Phase 1: 2-step-fused Chen, 512 stolen tasks =============
    // Step increments read directly from smem d[] (broadcast LDS) to keep
    // regs under the 85 cap (no a8/b8 register arrays).
    {
        const int l = tid & 7, k = (tid >> 3) & 7, j0 = tid >> 6;
        float* d   = sm;          // 256 = [32][8]
        float* cb0 = sm + 256;    // c2 [0,64), c3 [64,576)
        float* cb1 = sm + 840;
        for (;;) {
            __syncthreads();
            if (tid == 0) s_task = (int)atomicAdd(&g_t1, 1u);
            __syncthreads();
            int task = s_task;
            if (task >= NTASK1) break;
            int b = task >> 6, seg = task & 63;

            {   // increments (one per thread: 32 steps x 8 ch = 256)
                int s = tid >> 3, ch = tid & 7;
                int t = seg * SEGST + s;
                float v;
                if (ch < CIN) {
                    float cur  = __ldg(&x[(b * TT + t) * CIN + ch]);
                    float prev = (t > 0) ? __ldg(&x[(b * TT + t - 1) * CIN + ch]) : 0.0f;
                    v = cur - prev;
                } else {
                    v = (t > 0) ? (1.0f / 2047.0f) : 0.0f;
                }
                d[tid] = v;
            }
            __syncthreads();

            float r4[16], c1r[8];
            // ---- iter 0: carry := F(d0, d1) ----
            {
                float al = d[l], bl = d[8 + l], ak = d[k], bk = d[8 + k];
                float bkbl = bk * bl;
                float w1 = ak * ((1.0f / 6.0f) * al + 0.5f * bl) + 0.5f * bkbl;
                float w2 = (1.0f / 6.0f) * bkbl;
                float aje = d[j0], bje = d[8 + j0], ajo = d[j0 + 4], bjo = d[8 + j0 + 4];
                float F3_e = aje * w1 + bje * w2;
                float F3_o = ajo * w1 + bjo * w2;
                float u4 = ak * ((1.0f / 24.0f) * al + (1.0f / 6.0f) * bl) + 0.25f * bkbl;
                float v4 = (1.0f / 6.0f) * bkbl;
                float ge = aje * u4 + bje * v4, he = (1.0f / 24.0f) * bje * bkbl;
                float go = ajo * u4 + bjo * v4, ho = (1.0f / 24.0f) * bjo * bkbl;
                #pragma unroll
                for (int m = 0; m < 16; m++)
                    r4[m] = d[m >> 1] * ((m & 1) ? go : ge)
                          + d[8 + (m >> 1)] * ((m & 1) ? ho : he);
                #pragma unroll
                for (int i = 0; i < 8; i++) c1r[i] = d[i] + d[8 + i];
                cb0[64 + tid] = F3_e;
                cb0[64 + tid + 256] = F3_o;
                if (tid < 64) {
                    int xx = tid >> 3, yy = tid & 7;
                    cb0[tid] = 0.5f * d[xx] * d[yy] + d[xx] * d[8 + yy]
                             + 0.5f * d[8 + xx] * d[8 + yy];
                }
                __syncthreads();
            }
            // ---- iters 1..15 ----
            for (int it = 1; it < 16; it++) {
                float* cc = (it & 1) ? cb0 : cb1;
                float* cn = (it & 1) ? cb1 : cb0;
                const float* da = d + 16 * it;
                const float* db = da + 8;
                float al = da[l], bl = db[l], ak = da[k], bk = db[k];
                float el = al + bl;
                float bkbl = bk * bl;
                float F2_kl = 0.5f * ak * al + ak * bl + 0.5f * bkbl;
                float w1 = ak * ((1.0f / 6.0f) * al + 0.5f * bl) + 0.5f * bkbl;
                float w2 = (1.0f / 6.0f) * bkbl;
                float aje = da[j0], bje = db[j0], ajo = da[j0 + 4], bjo = db[j0 + 4];
                float F3_e = aje * w1 + bje * w2;
                float F3_o = ajo * w1 + bjo * w2;
                float u4 = ak * ((1.0f / 24.0f) * al + (1.0f / 6.0f) * bl) + 0.25f * bkbl;
                float v4 = (1.0f / 6.0f) * bkbl;
                float ge = aje * u4 + bje * v4, he = (1.0f / 24.0f) * bje * bkbl;
                float go = ajo * u4 + bjo * v4, ho = (1.0f / 24.0f) * bjo * bkbl;
                #pragma unroll
                for (int m = 0; m < 16; m++) {
                    float c3v = cc[64 + (tid >> 3) + 32 * m];
                    float c2v = cc[(tid >> 6) + 4 * m];
                    float F3j = (m & 1) ? F3_o : F3_e;
                    float F4m = da[m >> 1] * ((m & 1) ? go : ge)
                              + db[m >> 1] * ((m & 1) ? ho : he);
                    r4[m] += F4m + c1r[m >> 1] * F3j + c2v * F2_kl + c3v * el;
                }
                float t3a = cc[64 + tid] + F3_e + cc[tid >> 3] * el + c1r[j0] * F2_kl;
                float t3b = cc[64 + tid + 256] + F3_o + cc[(tid >> 3) + 32] * el
                          + c1r[j0 + 4] * F2_kl;
                float t2v = 0.0f;
                if (tid < 64) {
                    int xx = tid >> 3, yy = tid & 7;
                    t2v = cc[tid] + 0.5f * da[xx] * da[yy] + da[xx] * db[yy]
                        + 0.5f * db[xx] * db[yy] + c1r[xx] * (da[yy] + db[yy]);
                }
                #pragma unroll
                for (int i = 0; i < 8; i++) c1r[i] += da[i] + db[i];
                cn[64 + tid] = t3a;
                cn[64 + tid + 256] = t3b;
                if (tid < 64) cn[tid] = t2v;
                __syncthreads();
                if ((it & 7) == 7) {   // chunk snapshot
                    float* o = g_bufB + (size_t)(b * NCH + seg * SEGC + (it >> 3)) * STRIDE;
                    o[O3 + tid] = t3a;
                    o[O3 + tid + 256] = t3b;
                    if (tid < 64) o[O2 + tid] = t2v;
                    if (tid < 8)  o[tid] = c1r[tid];
                    #pragma unroll
                    for (int m = 0; m < 16; m++) o[O4 + tid + 256 * m] = r4[m];
                }
            }
        }
    }
    gsync(1);

    // ============ Phase 2: Sklansky over 64 segment totals ==================
    // 6 rounds; 256 merges per round, done by blocks 0..255 (rest idle).
    for (int r = 0; r < 6; r++) {
        if (blk < 256) {
            int b = blk >> 5, g = blk & 31;
            int span = 1 << r;
            int base = (g >> r) << (r + 1);
            int e_src = base + span - 1;
            int e_dst = base + span + (g & (span - 1));
            bool bnew = (g & (span - 1)) == 0;
            const float* A = (r == 0)
                ? g_bufB + (size_t)(b * NCH + e_src * SEGC + SEGC - 1) * STRIDE
                : g_T + (size_t)(b * NSEG2 + e_src) * STRIDE;
            const float* Bp = bnew
                ? g_bufB + (size_t)(b * NCH + e_dst * SEGC + SEGC - 1) * STRIDE
                : g_T + (size_t)(b * NSEG2 + e_dst) * STRIDE;
            float* Od = g_T + (size_t)(b * NSEG2 + e_dst) * STRIDE;
            __syncthreads();
            ta_merge(A, Bp, Od, sm, tid);
        }
        gsync(2 + r);
    }

    // ============ Phase 3: apply + log, 1024 stolen tasks ===================
    for (;;) {
        __syncthreads();
        if (tid == 0) s_task = (int)atomicAdd(&g_t3, 1u);
        __syncthreads();
        int task = s_task;
        if (task >= NTASK3) break;
        apply_one(task, sm, tid);
    }
    gsync(8);

    // ============ Phase 4: pool + GEMV partials, 256 stolen tasks ===========
    for (;;) {
        __syncthreads();
        if (tid == 0) s_task = (int)atomicAdd(&g_t4, 1u);
        __syncthreads();
        int task = s_task;
        if (task >= NTASK4) break;
        int b = task >> 5, sl = task & 31;
        int i0 = sl * SLW;
        int len = SIZE - i0; if (len > SLW) len = SLW;
        float* pv = sm;
        if (tid < len) {
            const float* p = g_bufA + (size_t)b * NCH * STRIDE + i0 + tid;
            float acc = 0.0f;
            #pragma unroll 8
            for (int n = 0; n < NCH; n++) acc += __ldcg(p + (size_t)n * STRIDE);
            pv[tid] = acc * (1.0f / NCH);
        }
        __syncthreads();
        float acc = 0.0f;
        for (int ii = 0; ii < len; ii++)
            acc = fmaf(pv[ii], __ldg(&W1[(size_t)(i0 + ii) * HDIM + tid]), acc);
        g_hp[(sl * BB + b) * HDIM + tid] = acc;
    }
    gsync(9);

    // ============ Final: MLP head (block 0) =================================
    if (blk == 0) {
        float* red = sm;
        __syncthreads();
        for (int bb = 0; bb < BB; bb++) {
            float h = 0.0f;
            #pragma unroll
            for (int sl2 = 0; sl2 < NSL; sl2++)
                h += __ldcg(&g_hp[(sl2 * BB + bb) * HDIM + tid]);
            float v = fmaxf(h + b1[tid], 0.0f) * W2[tid];
            red[tid] = v; __syncthreads();
            for (int s2 = 128; s2 > 0; s2 >>= 1) {
                if (tid < s2) red[tid] += red[tid + s2];
                __syncthreads();
            }
            if (tid == 0) out[bb] = red[0] + b2[0];
            __syncthreads();
        }
        if (tid == 0) { g_bar = 0u; g_t1 = 0u; g_t3 = 0u; g_t4 = 0u; }
    }
}

// ---------------------------------------------------------------------------
extern "C" void kernel_launch(void* const* d_in, const int* in_sizes, int n_in,
                              void* d_out, int out_size)
{
    const float* x  = (const float*)d_in[0];
    const float* W1 = (const float*)d_in[1];
    const float* b1 = (const float*)d_in[2];
    const float* W2 = (const float*)d_in[3];
    const float* b2 = (const float*)d_in[4];
    float* out = (float*)d_out;

    (void)in_sizes; (void)n_in; (void)out_size;

    k_fused<<<NBLK, NT>>>(x, W1, b1, W2, b2, out);
}